// round 14
// baseline (speedup 1.0000x reference)
#include <cuda_runtime.h>

#define KK 20
#define CC 96
#define TILE_P 32
#define NG 8
#define GROUP 48                 // 4 kt * 12 ct
#define NTHREADS (NG * GROUP)    // 384
#define K_T 5
#define C_T 8
#define SPLITS 37
#define MAX_BLOCKS 400
#define NSTAGE 5

// dynamic smem layout (floats)
#define OFF_MBAR   0                                   // 16 floats (5 u64 + pad)
#define OFF_RAWF   16                                  // NSTAGE*TILE_P*CC = 15360
#define OFF_RAWP   (OFF_RAWF + NSTAGE * TILE_P * CC)   // NSTAGE*TILE_P*KK = 3200
#define OFF_EP     (OFF_RAWP + NSTAGE * TILE_P * KK)   // 2*TILE_P*32 = 2048
#define OFF_DK     (OFF_EP + 2 * TILE_P * 32)          // 32
#define SMEM_FLOATS (OFF_DK + 32)
#define SMEM_BYTES (SMEM_FLOATS * 4)

__device__ float g_part[MAX_BLOCKS * KK * CC];
__device__ float g_pden[MAX_BLOCKS * KK];

// ---------------- f32x2 helpers ----------------
__device__ __forceinline__ unsigned long long pack2(float lo, float hi) {
    unsigned long long r;
    asm("mov.b64 %0, {%1, %2};" : "=l"(r) : "f"(lo), "f"(hi));
    return r;
}
__device__ __forceinline__ unsigned long long fma2(unsigned long long a,
                                                   unsigned long long b,
                                                   unsigned long long c) {
    unsigned long long d;
    asm("fma.rn.f32x2 %0, %1, %2, %3;" : "=l"(d) : "l"(a), "l"(b), "l"(c));
    return d;
}
__device__ __forceinline__ void unpack2(unsigned long long x, float& lo, float& hi) {
    asm("mov.b64 {%0, %1}, %2;" : "=f"(lo), "=f"(hi) : "l"(x));
}

// ---------------- TMA bulk + mbarrier helpers ----------------
__device__ __forceinline__ unsigned smem_u32(const void* p) {
    return (unsigned)__cvta_generic_to_shared(p);
}
__device__ __forceinline__ void mbar_init(unsigned mbar, unsigned count) {
    asm volatile("mbarrier.init.shared.b64 [%0], %1;" :: "r"(mbar), "r"(count) : "memory");
}
__device__ __forceinline__ void mbar_expect_tx(unsigned mbar, unsigned bytes) {
    asm volatile("mbarrier.arrive.expect_tx.shared.b64 _, [%0], %1;"
                 :: "r"(mbar), "r"(bytes) : "memory");
}
__device__ __forceinline__ void mbar_wait(unsigned mbar, unsigned parity) {
    asm volatile(
        "{\n\t.reg .pred P;\n"
        "WAIT_%=:\n\t"
        "mbarrier.try_wait.parity.acquire.cta.shared::cta.b64 P, [%0], %1, 0x989680;\n\t"
        "@!P bra WAIT_%=;\n\t"
        "}"
        :: "r"(mbar), "r"(parity) : "memory");
}
__device__ __forceinline__ void bulk_g2s(unsigned dst, const void* src,
                                         unsigned bytes, unsigned mbar) {
    asm volatile(
        "cp.async.bulk.shared::cta.global.mbarrier::complete_tx::bytes [%0], [%1], %2, [%3];"
        :: "r"(dst), "l"(src), "r"(bytes), "r"(mbar) : "memory");
}

// warp-cooperative lower_bound on sorted int array
__device__ __forceinline__ int lower_bound_warp(const int* __restrict__ a,
                                                int n, int key) {
    int lane = threadIdx.x & 31;
    int lo = 0, hi = n;
    while (lo < hi) {
        int len = hi - lo;
        int chunk = (len + 31) >> 5;
        int pos = lo + lane * chunk;
        bool pred = (pos < hi) && (a[pos] < key);
        unsigned m = __ballot_sync(0xffffffffu, pred);
        int t = __popc(m);
        if (t == 0) { hi = lo; break; }
        int nlo = lo + (t - 1) * chunk + 1;
        int nhi = (t < 32) ? min(lo + t * chunk, hi) : hi;
        lo = nlo; hi = nhi;
    }
    return lo;
}

// ---------------------------------------------------------------------------
__global__ void __launch_bounds__(NTHREADS, 2)
gather_kernel(const float* __restrict__ feats,
              const float* __restrict__ probs,
              const int*   __restrict__ bidx,
              int N) {
    extern __shared__ float smem[];
    unsigned long long* mbar = reinterpret_cast<unsigned long long*>(smem + OFF_MBAR);
    float* raw_f = smem + OFF_RAWF;     // [NSTAGE][TILE_P][CC]  (scratch after loop)
    float* raw_p = smem + OFF_RAWP;     // [NSTAGE][TILE_P][KK]
    float* sh_ep = smem + OFF_EP;       // [2][TILE_P][32] kt-padded exp
    float* sh_dk = smem + OFF_DK;       // [KK]
    __shared__ int sh_off[2];

    const int tid = threadIdx.x;
    const int b = blockIdx.x / SPLITS;
    const int s = blockIdx.x % SPLITS;

    if (tid < 32) {
        int lo0 = lower_bound_warp(bidx, N, b);
        int lo1 = lower_bound_warp(bidx, N, b + 1);
        if (tid == 0) { sh_off[0] = lo0; sh_off[1] = lo1; }
    }
    if (tid < KK) sh_dk[tid] = 0.0f;
    if (tid == 0) {
#pragma unroll
        for (int i = 0; i < NSTAGE; i++) mbar_init(smem_u32(&mbar[i]), 1);
    }
    __syncthreads();

    const int seg0 = sh_off[0];
    const int seg1 = sh_off[1];
    const int len  = seg1 - seg0;
    const int r0 = seg0 + (int)((long long)len * s / SPLITS);
    const int r1 = seg0 + (int)((long long)len * (s + 1) / SPLITS);
    const int T  = (r1 - r0 + TILE_P - 1) / TILE_P;

    const int g  = tid / GROUP;         // 0..7
    const int gt = tid % GROUP;
    const int kt = gt / 12;             // 0..3
    const int ct = gt % 12;             // 0..11

    unsigned long long acc[K_T][4];
#pragma unroll
    for (int j = 0; j < K_T; j++)
#pragma unroll
        for (int q = 0; q < 4; q++) acc[j][q] = 0ULL;
    float dacc0 = 0.0f, dacc1 = 0.0f;

    // ---- prologue: issue up to NSTAGE tiles ----
    if (tid == 0) {
        int np = min(NSTAGE, T);
        for (int tt = 0; tt < np; tt++) {
            int base = r0 + tt * TILE_P;
            int rows = min(TILE_P, N - base);
            unsigned fb = rows * CC * 4;
            unsigned pb = rows * KK * 4;
            unsigned mb = smem_u32(&mbar[tt]);
            mbar_expect_tx(mb, fb + pb);
            bulk_g2s(smem_u32(&raw_f[tt * TILE_P * CC]),
                     feats + (long long)base * CC, fb, mb);
            bulk_g2s(smem_u32(&raw_p[tt * TILE_P * KK]),
                     probs + (long long)base * KK, pb, mb);
        }
    }

    // ---- prologue: exp of tile 0 into ep buf 0 ----
    if (T > 0) {
        mbar_wait(smem_u32(&mbar[0]), 0);
        {
            int v = tid;
            int p = v / KK, k = v % KK;
            float e = (r0 + p < r1) ? __expf(raw_p[v]) : 0.0f;
            sh_ep[p * 32 + (k / K_T) * 8 + (k % K_T)] = e;
            dacc0 += e;
            if (tid < TILE_P * KK - NTHREADS) {
                v = tid + NTHREADS;
                p = v / KK; k = v % KK;
                e = (r0 + p < r1) ? __expf(raw_p[v]) : 0.0f;
                sh_ep[p * 32 + (k / K_T) * 8 + (k % K_T)] = e;
                dacc1 += e;
            }
        }
    }
    __syncthreads();

    int stW = 1, parW = 0;       // cursor for wait of tile t+1
    int stC = 0;                 // stage of tile t
    int isSt = 0;                // stage for issue of tile t+NSTAGE

    for (int t = 0; t < T; t++) {
        // overlap: exp of tile t+1 (other ep buffer) with FFMA of tile t
        if (t + 1 < T) {
            mbar_wait(smem_u32(&mbar[stW]), parW);
            const int nb = r0 + (t + 1) * TILE_P;
            float* ep = sh_ep + ((t + 1) & 1) * (TILE_P * 32);
            const float* rp = raw_p + stW * TILE_P * KK;
            int v = tid;
            int p = v / KK, k = v % KK;
            float e = (nb + p < r1) ? __expf(rp[v]) : 0.0f;
            ep[p * 32 + (k / K_T) * 8 + (k % K_T)] = e;
            dacc0 += e;
            if (tid < TILE_P * KK - NTHREADS) {
                v = tid + NTHREADS;
                p = v / KK; k = v % KK;
                e = (nb + p < r1) ? __expf(rp[v]) : 0.0f;
                ep[p * 32 + (k / K_T) * 8 + (k % K_T)] = e;
                dacc1 += e;
            }
        }

        // ---- FFMA over tile t (4 points per thread) ----
        {
            const float* ep = sh_ep + (t & 1) * (TILE_P * 32);
            const float* rf = raw_f + stC * TILE_P * CC;
#pragma unroll
            for (int p = 0; p < TILE_P / NG; p++) {
                const int pp = g * (TILE_P / NG) + p;
                const ulonglong2* rowf =
                    reinterpret_cast<const ulonglong2*>(&rf[pp * CC + ct * C_T]);
                ulonglong2 fA = rowf[0];
                ulonglong2 fB = rowf[1];
                float4 e03 = *reinterpret_cast<const float4*>(&ep[pp * 32 + kt * 8]);
                float  e4  = ep[pp * 32 + kt * 8 + 4];
                unsigned long long e2[K_T];
                e2[0] = pack2(e03.x, e03.x);
                e2[1] = pack2(e03.y, e03.y);
                e2[2] = pack2(e03.z, e03.z);
                e2[3] = pack2(e03.w, e03.w);
                e2[4] = pack2(e4, e4);
#pragma unroll
                for (int j = 0; j < K_T; j++) {
                    acc[j][0] = fma2(e2[j], fA.x, acc[j][0]);
                    acc[j][1] = fma2(e2[j], fA.y, acc[j][1]);
                    acc[j][2] = fma2(e2[j], fB.x, acc[j][2]);
                    acc[j][3] = fma2(e2[j], fB.y, acc[j][3]);
                }
            }
        }
        __syncthreads();   // tile t raw_f consumed; exp(t+1) visible for next iter

        // issue tile t+NSTAGE into the just-freed stage
        if (tid == 0 && t + NSTAGE < T) {
            int nb = r0 + (t + NSTAGE) * TILE_P;
            int rows = min(TILE_P, N - nb);
            unsigned fb = rows * CC * 4;
            unsigned pb = rows * KK * 4;
            unsigned mb = smem_u32(&mbar[isSt]);
            mbar_expect_tx(mb, fb + pb);
            bulk_g2s(smem_u32(&raw_f[isSt * TILE_P * CC]),
                     feats + (long long)nb * CC, fb, mb);
            bulk_g2s(smem_u32(&raw_p[isSt * TILE_P * KK]),
                     probs + (long long)nb * KK, pb, mb);
        }
        if (++stW == NSTAGE) { stW = 0; parW ^= 1; }
        if (++stC == NSTAGE) stC = 0;
        if (++isSt == NSTAGE) isSt = 0;
    }

    // ---- denom reduction ----
    atomicAdd(&sh_dk[tid % KK], dacc0);
    if (tid < TILE_P * KK - NTHREADS)
        atomicAdd(&sh_dk[(tid + NTHREADS) % KK], dacc1);

    // ---- epilogue: all 8 groups dump to scratch (reuse raw_f), one sync, sum ----
    float* scratch = raw_f;   // NSTAGE*TILE_P*CC = 15360 = NG * KK * CC floats
    {
        const int base = g * (KK * CC) + kt * K_T * CC + ct * C_T;
#pragma unroll
        for (int j = 0; j < K_T; j++) {
            float a0, a1, a2, a3, a4, a5, a6, a7;
            unpack2(acc[j][0], a0, a1);
            unpack2(acc[j][1], a2, a3);
            unpack2(acc[j][2], a4, a5);
            unpack2(acc[j][3], a6, a7);
            *reinterpret_cast<float4*>(&scratch[base + j * CC]) =
                make_float4(a0, a1, a2, a3);
            *reinterpret_cast<float4*>(&scratch[base + j * CC + 4]) =
                make_float4(a4, a5, a6, a7);
        }
    }
    __syncthreads();

    {
        float* outp = g_part + blockIdx.x * (KK * CC);
#pragma unroll
        for (int i = 0; i < (KK * CC) / NTHREADS; i++) {
            int o = tid + i * NTHREADS;
            float sum = 0.0f;
#pragma unroll
            for (int gg = 0; gg < NG; gg++)
                sum += scratch[gg * (KK * CC) + o];
            outp[o] = sum;
        }
    }
    if (tid < KK)
        g_pden[blockIdx.x * KK + tid] = sh_dk[tid];
}

// ---------------------------------------------------------------------------
// reduce v4: one block per (b,k); 8 s-slices x 96 channels; smem combine.
// ---------------------------------------------------------------------------
__global__ void __launch_bounds__(768)
reduce_kernel(float* __restrict__ out) {
    const int bk = blockIdx.x;          // B*KK blocks
    const int b = bk / KK, k = bk % KK;
    const int sg = threadIdx.x / CC;    // 0..7
    const int c  = threadIdx.x % CC;

    __shared__ float red[8][CC];
    __shared__ float den[8];

    float v = 0.0f, d = 0.0f;
    for (int s = sg; s < SPLITS; s += 8) {
        v += g_part[((b * SPLITS + s) * KK + k) * CC + c];
        if (c == 0) d += g_pden[(b * SPLITS + s) * KK + k];
    }
    red[sg][c] = v;
    if (c == 0) den[sg] = d;
    __syncthreads();

    if (threadIdx.x < CC) {
        float vv = 0.0f, dd = 0.0f;
#pragma unroll
        for (int i = 0; i < 8; i++) { vv += red[i][c]; dd += den[i]; }
        out[bk * CC + c] = (dd > 0.0f) ? vv / dd : 0.0f;
    }
}

// ---------------------------------------------------------------------------
extern "C" void kernel_launch(void* const* d_in, const int* in_sizes, int n_in,
                              void* d_out, int out_size) {
    const float* feats = (const float*)d_in[0];   // [N, C]
    const float* probs = (const float*)d_in[1];   // [N, K]
    const int*   bidx  = (const int*)d_in[3];     // [N], sorted
    float* out = (float*)d_out;                   // [B, K, C]

    const int N = in_sizes[3];
    const int B = out_size / (KK * CC);

    cudaFuncSetAttribute(gather_kernel,
                         cudaFuncAttributeMaxDynamicSharedMemorySize, SMEM_BYTES);
    gather_kernel<<<B * SPLITS, NTHREADS, SMEM_BYTES>>>(feats, probs, bidx, N);
    reduce_kernel<<<B * KK, 768>>>(out);
}

// round 15
// speedup vs baseline: 1.0010x; 1.0010x over previous
#include <cuda_runtime.h>

#define KK 20
#define CC 96
#define TILE_P 32
#define NG 8
#define GROUP 48                 // 4 kt * 12 ct
#define NTHREADS (NG * GROUP)    // 384
#define K_T 5
#define C_T 8
#define SPLITS 37
#define MAX_BLOCKS 400
#define NSTAGE 5

// dynamic smem layout (floats)
#define OFF_MBAR   0                                   // 16 floats (5 u64 + pad)
#define OFF_RAWF   16                                  // NSTAGE*TILE_P*CC = 15360
#define OFF_RAWP   (OFF_RAWF + NSTAGE * TILE_P * CC)   // NSTAGE*TILE_P*KK = 3200
#define OFF_EP     (OFF_RAWP + NSTAGE * TILE_P * KK)   // 2*TILE_P*32 = 2048
#define OFF_DK     (OFF_EP + 2 * TILE_P * 32)          // 32
#define SMEM_FLOATS (OFF_DK + 32)
#define SMEM_BYTES (SMEM_FLOATS * 4)

__device__ float g_part[MAX_BLOCKS * KK * CC];
__device__ float g_pden[MAX_BLOCKS * KK];

// ---------------- f32x2 helpers ----------------
__device__ __forceinline__ unsigned long long pack2(float lo, float hi) {
    unsigned long long r;
    asm("mov.b64 %0, {%1, %2};" : "=l"(r) : "f"(lo), "f"(hi));
    return r;
}
__device__ __forceinline__ unsigned long long fma2(unsigned long long a,
                                                   unsigned long long b,
                                                   unsigned long long c) {
    unsigned long long d;
    asm("fma.rn.f32x2 %0, %1, %2, %3;" : "=l"(d) : "l"(a), "l"(b), "l"(c));
    return d;
}
__device__ __forceinline__ void unpack2(unsigned long long x, float& lo, float& hi) {
    asm("mov.b64 {%0, %1}, %2;" : "=f"(lo), "=f"(hi) : "l"(x));
}

// ---------------- TMA bulk + mbarrier helpers ----------------
__device__ __forceinline__ unsigned smem_u32(const void* p) {
    return (unsigned)__cvta_generic_to_shared(p);
}
__device__ __forceinline__ void mbar_init(unsigned mbar, unsigned count) {
    asm volatile("mbarrier.init.shared.b64 [%0], %1;" :: "r"(mbar), "r"(count) : "memory");
}
__device__ __forceinline__ void mbar_expect_tx(unsigned mbar, unsigned bytes) {
    asm volatile("mbarrier.arrive.expect_tx.shared.b64 _, [%0], %1;"
                 :: "r"(mbar), "r"(bytes) : "memory");
}
__device__ __forceinline__ void mbar_wait(unsigned mbar, unsigned parity) {
    asm volatile(
        "{\n\t.reg .pred P;\n"
        "WAIT_%=:\n\t"
        "mbarrier.try_wait.parity.acquire.cta.shared::cta.b64 P, [%0], %1, 0x989680;\n\t"
        "@!P bra WAIT_%=;\n\t"
        "}"
        :: "r"(mbar), "r"(parity) : "memory");
}
__device__ __forceinline__ void bulk_g2s(unsigned dst, const void* src,
                                         unsigned bytes, unsigned mbar) {
    asm volatile(
        "cp.async.bulk.shared::cta.global.mbarrier::complete_tx::bytes [%0], [%1], %2, [%3];"
        :: "r"(dst), "l"(src), "r"(bytes), "r"(mbar) : "memory");
}

// warp-cooperative lower_bound on sorted int array
__device__ __forceinline__ int lower_bound_warp(const int* __restrict__ a,
                                                int n, int key) {
    int lane = threadIdx.x & 31;
    int lo = 0, hi = n;
    while (lo < hi) {
        int len = hi - lo;
        int chunk = (len + 31) >> 5;
        int pos = lo + lane * chunk;
        bool pred = (pos < hi) && (a[pos] < key);
        unsigned m = __ballot_sync(0xffffffffu, pred);
        int t = __popc(m);
        if (t == 0) { hi = lo; break; }
        int nlo = lo + (t - 1) * chunk + 1;
        int nhi = (t < 32) ? min(lo + t * chunk, hi) : hi;
        lo = nlo; hi = nhi;
    }
    return lo;
}

// ---------------------------------------------------------------------------
__global__ void __launch_bounds__(NTHREADS, 2)
gather_kernel(const float* __restrict__ feats,
              const float* __restrict__ probs,
              const int*   __restrict__ bidx,
              int N) {
    extern __shared__ float smem[];
    unsigned long long* mbar = reinterpret_cast<unsigned long long*>(smem + OFF_MBAR);
    float* raw_f = smem + OFF_RAWF;     // [NSTAGE][TILE_P][CC]  (scratch after loop)
    float* raw_p = smem + OFF_RAWP;     // [NSTAGE][TILE_P][KK]
    float* sh_ep = smem + OFF_EP;       // [2][TILE_P][32] kt-padded exp
    float* sh_dk = smem + OFF_DK;       // [KK]
    __shared__ int sh_off[2];

    const int tid = threadIdx.x;
    const int b = blockIdx.x / SPLITS;
    const int s = blockIdx.x % SPLITS;

    if (tid < 32) {
        int lo0 = lower_bound_warp(bidx, N, b);
        int lo1 = lower_bound_warp(bidx, N, b + 1);
        if (tid == 0) { sh_off[0] = lo0; sh_off[1] = lo1; }
    }
    if (tid < KK) sh_dk[tid] = 0.0f;
    if (tid == 0) {
#pragma unroll
        for (int i = 0; i < NSTAGE; i++) mbar_init(smem_u32(&mbar[i]), 1);
    }
    __syncthreads();

    const int seg0 = sh_off[0];
    const int seg1 = sh_off[1];
    const int len  = seg1 - seg0;
    const int r0 = seg0 + (int)((long long)len * s / SPLITS);
    const int r1 = seg0 + (int)((long long)len * (s + 1) / SPLITS);
    const int T  = (r1 - r0 + TILE_P - 1) / TILE_P;

    const int g  = tid / GROUP;         // 0..7
    const int gt = tid % GROUP;
    const int kt = gt / 12;             // 0..3
    const int ct = gt % 12;             // 0..11

    unsigned long long acc[K_T][4];
#pragma unroll
    for (int j = 0; j < K_T; j++)
#pragma unroll
        for (int q = 0; q < 4; q++) acc[j][q] = 0ULL;
    float dacc0 = 0.0f, dacc1 = 0.0f;

    // ---- prologue: issue up to NSTAGE tiles ----
    if (tid == 0) {
        int np = min(NSTAGE, T);
        for (int tt = 0; tt < np; tt++) {
            int base = r0 + tt * TILE_P;
            int rows = min(TILE_P, N - base);
            unsigned fb = rows * CC * 4;
            unsigned pb = rows * KK * 4;
            unsigned mb = smem_u32(&mbar[tt]);
            mbar_expect_tx(mb, fb + pb);
            bulk_g2s(smem_u32(&raw_f[tt * TILE_P * CC]),
                     feats + (long long)base * CC, fb, mb);
            bulk_g2s(smem_u32(&raw_p[tt * TILE_P * KK]),
                     probs + (long long)base * KK, pb, mb);
        }
    }

    // ---- prologue: exp of tile 0 into ep buf 0 ----
    if (T > 0) {
        mbar_wait(smem_u32(&mbar[0]), 0);
        {
            int v = tid;
            int p = v / KK, k = v % KK;
            float e = (r0 + p < r1) ? __expf(raw_p[v]) : 0.0f;
            sh_ep[p * 32 + (k / K_T) * 8 + (k % K_T)] = e;
            dacc0 += e;
            if (tid < TILE_P * KK - NTHREADS) {
                v = tid + NTHREADS;
                p = v / KK; k = v % KK;
                e = (r0 + p < r1) ? __expf(raw_p[v]) : 0.0f;
                sh_ep[p * 32 + (k / K_T) * 8 + (k % K_T)] = e;
                dacc1 += e;
            }
        }
    }
    __syncthreads();

    int stW = 1, parW = 0;       // cursor for wait of tile t+1
    int stC = 0;                 // stage of tile t
    int isSt = 0;                // stage for issue of tile t+NSTAGE

    for (int t = 0; t < T; t++) {
        // overlap: exp of tile t+1 (other ep buffer) with FFMA of tile t
        if (t + 1 < T) {
            mbar_wait(smem_u32(&mbar[stW]), parW);
            const int nb = r0 + (t + 1) * TILE_P;
            float* ep = sh_ep + ((t + 1) & 1) * (TILE_P * 32);
            const float* rp = raw_p + stW * TILE_P * KK;
            int v = tid;
            int p = v / KK, k = v % KK;
            float e = (nb + p < r1) ? __expf(rp[v]) : 0.0f;
            ep[p * 32 + (k / K_T) * 8 + (k % K_T)] = e;
            dacc0 += e;
            if (tid < TILE_P * KK - NTHREADS) {
                v = tid + NTHREADS;
                p = v / KK; k = v % KK;
                e = (nb + p < r1) ? __expf(rp[v]) : 0.0f;
                ep[p * 32 + (k / K_T) * 8 + (k % K_T)] = e;
                dacc1 += e;
            }
        }

        // ---- FFMA over tile t (4 points per thread) ----
        {
            const float* ep = sh_ep + (t & 1) * (TILE_P * 32);
            const float* rf = raw_f + stC * TILE_P * CC;
#pragma unroll
            for (int p = 0; p < TILE_P / NG; p++) {
                const int pp = g * (TILE_P / NG) + p;
                const ulonglong2* rowf =
                    reinterpret_cast<const ulonglong2*>(&rf[pp * CC + ct * C_T]);
                ulonglong2 fA = rowf[0];
                ulonglong2 fB = rowf[1];
                float4 e03 = *reinterpret_cast<const float4*>(&ep[pp * 32 + kt * 8]);
                float  e4  = ep[pp * 32 + kt * 8 + 4];
                unsigned long long e2[K_T];
                e2[0] = pack2(e03.x, e03.x);
                e2[1] = pack2(e03.y, e03.y);
                e2[2] = pack2(e03.z, e03.z);
                e2[3] = pack2(e03.w, e03.w);
                e2[4] = pack2(e4, e4);
#pragma unroll
                for (int j = 0; j < K_T; j++) {
                    acc[j][0] = fma2(e2[j], fA.x, acc[j][0]);
                    acc[j][1] = fma2(e2[j], fA.y, acc[j][1]);
                    acc[j][2] = fma2(e2[j], fB.x, acc[j][2]);
                    acc[j][3] = fma2(e2[j], fB.y, acc[j][3]);
                }
            }
        }
        __syncthreads();   // tile t raw_f consumed; exp(t+1) visible for next iter

        // issue tile t+NSTAGE into the just-freed stage
        if (tid == 0 && t + NSTAGE < T) {
            int nb = r0 + (t + NSTAGE) * TILE_P;
            int rows = min(TILE_P, N - nb);
            unsigned fb = rows * CC * 4;
            unsigned pb = rows * KK * 4;
            unsigned mb = smem_u32(&mbar[isSt]);
            mbar_expect_tx(mb, fb + pb);
            bulk_g2s(smem_u32(&raw_f[isSt * TILE_P * CC]),
                     feats + (long long)nb * CC, fb, mb);
            bulk_g2s(smem_u32(&raw_p[isSt * TILE_P * KK]),
                     probs + (long long)nb * KK, pb, mb);
        }
        if (++stW == NSTAGE) { stW = 0; parW ^= 1; }
        if (++stC == NSTAGE) stC = 0;
        if (++isSt == NSTAGE) isSt = 0;
    }

    // ---- denom reduction ----
    atomicAdd(&sh_dk[tid % KK], dacc0);
    if (tid < TILE_P * KK - NTHREADS)
        atomicAdd(&sh_dk[(tid + NTHREADS) % KK], dacc1);

    // ---- epilogue: all 8 groups dump to scratch (reuse raw_f), one sync, sum ----
    float* scratch = raw_f;   // NSTAGE*TILE_P*CC = 15360 = NG * KK * CC floats
    {
        const int base = g * (KK * CC) + kt * K_T * CC + ct * C_T;
#pragma unroll
        for (int j = 0; j < K_T; j++) {
            float a0, a1, a2, a3, a4, a5, a6, a7;
            unpack2(acc[j][0], a0, a1);
            unpack2(acc[j][1], a2, a3);
            unpack2(acc[j][2], a4, a5);
            unpack2(acc[j][3], a6, a7);
            *reinterpret_cast<float4*>(&scratch[base + j * CC]) =
                make_float4(a0, a1, a2, a3);
            *reinterpret_cast<float4*>(&scratch[base + j * CC + 4]) =
                make_float4(a4, a5, a6, a7);
        }
    }
    __syncthreads();

    {
        float* outp = g_part + blockIdx.x * (KK * CC);
#pragma unroll
        for (int i = 0; i < (KK * CC) / NTHREADS; i++) {
            int o = tid + i * NTHREADS;
            float sum = 0.0f;
#pragma unroll
            for (int gg = 0; gg < NG; gg++)
                sum += scratch[gg * (KK * CC) + o];
            outp[o] = sum;
        }
    }
    if (tid < KK)
        g_pden[blockIdx.x * KK + tid] = sh_dk[tid];
}

// ---------------------------------------------------------------------------
// reduce v4: one block per (b,k); 8 s-slices x 96 channels; smem combine.
// ---------------------------------------------------------------------------
__global__ void __launch_bounds__(768)
reduce_kernel(float* __restrict__ out) {
    const int bk = blockIdx.x;          // B*KK blocks
    const int b = bk / KK, k = bk % KK;
    const int sg = threadIdx.x / CC;    // 0..7
    const int c  = threadIdx.x % CC;

    __shared__ float red[8][CC];
    __shared__ float den[8];

    float v = 0.0f, d = 0.0f;
    for (int s = sg; s < SPLITS; s += 8) {
        v += g_part[((b * SPLITS + s) * KK + k) * CC + c];
        if (c == 0) d += g_pden[(b * SPLITS + s) * KK + k];
    }
    red[sg][c] = v;
    if (c == 0) den[sg] = d;
    __syncthreads();

    if (threadIdx.x < CC) {
        float vv = 0.0f, dd = 0.0f;
#pragma unroll
        for (int i = 0; i < 8; i++) { vv += red[i][c]; dd += den[i]; }
        out[bk * CC + c] = (dd > 0.0f) ? vv / dd : 0.0f;
    }
}

// ---------------------------------------------------------------------------
extern "C" void kernel_launch(void* const* d_in, const int* in_sizes, int n_in,
                              void* d_out, int out_size) {
    const float* feats = (const float*)d_in[0];   // [N, C]
    const float* probs = (const float*)d_in[1];   // [N, K]
    const int*   bidx  = (const int*)d_in[3];     // [N], sorted
    float* out = (float*)d_out;                   // [B, K, C]

    const int N = in_sizes[3];
    const int B = out_size / (KK * CC);

    cudaFuncSetAttribute(gather_kernel,
                         cudaFuncAttributeMaxDynamicSharedMemorySize, SMEM_BYTES);
    gather_kernel<<<B * SPLITS, NTHREADS, SMEM_BYTES>>>(feats, probs, bidx, N);
    reduce_kernel<<<B * KK, 768>>>(out);
}

// round 16
// speedup vs baseline: 1.0218x; 1.0208x over previous
#include <cuda_runtime.h>

#define KK 20
#define CC 96
#define TILE_P 32
#define NG 8
#define GROUP 48                 // 4 kt * 12 ct
#define NTHREADS (NG * GROUP)    // 384
#define K_T 5
#define C_T 8
#define SPLITS 37
#define MAX_BLOCKS 400
#define NSTAGE 5

// dynamic smem layout (floats)
#define OFF_MBAR   0                                   // 16 floats (5 u64 + pad)
#define OFF_RAWF   16                                  // NSTAGE*TILE_P*CC = 15360
#define OFF_RAWP   (OFF_RAWF + NSTAGE * TILE_P * CC)   // NSTAGE*TILE_P*KK = 3200
#define OFF_EP     (OFF_RAWP + NSTAGE * TILE_P * KK)   // 2*TILE_P*32 = 2048
#define OFF_DK     (OFF_EP + 2 * TILE_P * 32)          // 32
#define SMEM_FLOATS (OFF_DK + 32)
#define SMEM_BYTES (SMEM_FLOATS * 4)

__device__ float g_part[MAX_BLOCKS * KK * CC];
__device__ float g_pden[MAX_BLOCKS * KK];

// ---------------- f32x2 helpers ----------------
__device__ __forceinline__ unsigned long long pack2(float lo, float hi) {
    unsigned long long r;
    asm("mov.b64 %0, {%1, %2};" : "=l"(r) : "f"(lo), "f"(hi));
    return r;
}
__device__ __forceinline__ unsigned long long fma2(unsigned long long a,
                                                   unsigned long long b,
                                                   unsigned long long c) {
    unsigned long long d;
    asm("fma.rn.f32x2 %0, %1, %2, %3;" : "=l"(d) : "l"(a), "l"(b), "l"(c));
    return d;
}
__device__ __forceinline__ void unpack2(unsigned long long x, float& lo, float& hi) {
    asm("mov.b64 {%0, %1}, %2;" : "=f"(lo), "=f"(hi) : "l"(x));
}

// ---------------- TMA bulk + mbarrier helpers ----------------
__device__ __forceinline__ unsigned smem_u32(const void* p) {
    return (unsigned)__cvta_generic_to_shared(p);
}
__device__ __forceinline__ void mbar_init(unsigned mbar, unsigned count) {
    asm volatile("mbarrier.init.shared.b64 [%0], %1;" :: "r"(mbar), "r"(count) : "memory");
}
__device__ __forceinline__ void mbar_expect_tx(unsigned mbar, unsigned bytes) {
    asm volatile("mbarrier.arrive.expect_tx.shared.b64 _, [%0], %1;"
                 :: "r"(mbar), "r"(bytes) : "memory");
}
__device__ __forceinline__ void mbar_wait(unsigned mbar, unsigned parity) {
    asm volatile(
        "{\n\t.reg .pred P;\n"
        "WAIT_%=:\n\t"
        "mbarrier.try_wait.parity.acquire.cta.shared::cta.b64 P, [%0], %1, 0x989680;\n\t"
        "@!P bra WAIT_%=;\n\t"
        "}"
        :: "r"(mbar), "r"(parity) : "memory");
}
__device__ __forceinline__ void bulk_g2s(unsigned dst, const void* src,
                                         unsigned bytes, unsigned mbar) {
    asm volatile(
        "cp.async.bulk.shared::cta.global.mbarrier::complete_tx::bytes [%0], [%1], %2, [%3];"
        :: "r"(dst), "l"(src), "r"(bytes), "r"(mbar) : "memory");
}

// warp-cooperative lower_bound on sorted int array
__device__ __forceinline__ int lower_bound_warp(const int* __restrict__ a,
                                                int n, int key) {
    int lane = threadIdx.x & 31;
    int lo = 0, hi = n;
    while (lo < hi) {
        int len = hi - lo;
        int chunk = (len + 31) >> 5;
        int pos = lo + lane * chunk;
        bool pred = (pos < hi) && (a[pos] < key);
        unsigned m = __ballot_sync(0xffffffffu, pred);
        int t = __popc(m);
        if (t == 0) { hi = lo; break; }
        int nlo = lo + (t - 1) * chunk + 1;
        int nhi = (t < 32) ? min(lo + t * chunk, hi) : hi;
        lo = nlo; hi = nhi;
    }
    return lo;
}

// ---------------------------------------------------------------------------
__global__ void __launch_bounds__(NTHREADS, 2)
gather_kernel(const float* __restrict__ feats,
              const float* __restrict__ probs,
              const int*   __restrict__ bidx,
              int N) {
    extern __shared__ float smem[];
    unsigned long long* mbar = reinterpret_cast<unsigned long long*>(smem + OFF_MBAR);
    float* raw_f = smem + OFF_RAWF;     // [NSTAGE][TILE_P][CC]  (scratch after loop)
    float* raw_p = smem + OFF_RAWP;     // [NSTAGE][TILE_P][KK]
    float* sh_ep = smem + OFF_EP;       // [2][TILE_P][32] kt-padded exp
    float* sh_dk = smem + OFF_DK;       // [KK]
    __shared__ int sh_off[2];

    const int tid = threadIdx.x;
    const int b = blockIdx.x / SPLITS;
    const int s = blockIdx.x % SPLITS;

    if (tid < 32) {
        int lo0 = lower_bound_warp(bidx, N, b);
        int lo1 = lower_bound_warp(bidx, N, b + 1);
        if (tid == 0) { sh_off[0] = lo0; sh_off[1] = lo1; }
    }
    if (tid < KK) sh_dk[tid] = 0.0f;
    if (tid == 0) {
#pragma unroll
        for (int i = 0; i < NSTAGE; i++) mbar_init(smem_u32(&mbar[i]), 1);
    }
    __syncthreads();

    const int seg0 = sh_off[0];
    const int seg1 = sh_off[1];
    const int len  = seg1 - seg0;
    const int r0 = seg0 + (int)((long long)len * s / SPLITS);
    const int r1 = seg0 + (int)((long long)len * (s + 1) / SPLITS);
    const int T  = (r1 - r0 + TILE_P - 1) / TILE_P;

    const int g  = tid / GROUP;         // 0..7
    const int gt = tid % GROUP;
    const int kt = gt / 12;             // 0..3
    const int ct = gt % 12;             // 0..11

    unsigned long long acc[K_T][4];
#pragma unroll
    for (int j = 0; j < K_T; j++)
#pragma unroll
        for (int q = 0; q < 4; q++) acc[j][q] = 0ULL;
    float dacc0 = 0.0f, dacc1 = 0.0f;

    // ---- prologue: issue up to NSTAGE tiles ----
    if (tid == 0) {
        int np = min(NSTAGE, T);
        for (int tt = 0; tt < np; tt++) {
            int base = r0 + tt * TILE_P;
            int rows = min(TILE_P, N - base);
            unsigned fb = rows * CC * 4;
            unsigned pb = rows * KK * 4;
            unsigned mb = smem_u32(&mbar[tt]);
            mbar_expect_tx(mb, fb + pb);
            bulk_g2s(smem_u32(&raw_f[tt * TILE_P * CC]),
                     feats + (long long)base * CC, fb, mb);
            bulk_g2s(smem_u32(&raw_p[tt * TILE_P * KK]),
                     probs + (long long)base * KK, pb, mb);
        }
    }

    // ---- prologue: exp of tile 0 into ep buf 0 ----
    if (T > 0) {
        mbar_wait(smem_u32(&mbar[0]), 0);
        {
            int v = tid;
            int p = v / KK, k = v % KK;
            float e = (r0 + p < r1) ? __expf(raw_p[v]) : 0.0f;
            sh_ep[p * 32 + (k / K_T) * 8 + (k % K_T)] = e;
            dacc0 += e;
            if (tid < TILE_P * KK - NTHREADS) {
                v = tid + NTHREADS;
                p = v / KK; k = v % KK;
                e = (r0 + p < r1) ? __expf(raw_p[v]) : 0.0f;
                sh_ep[p * 32 + (k / K_T) * 8 + (k % K_T)] = e;
                dacc1 += e;
            }
        }
    }
    __syncthreads();

    int stW = 1, parW = 0;       // cursor for wait of tile t+1
    int stC = 0;                 // stage of tile t
    int isSt = 0;                // stage for issue of tile t+NSTAGE

    for (int t = 0; t < T; t++) {
        // overlap: exp of tile t+1 (other ep buffer) with FFMA of tile t
        if (t + 1 < T) {
            mbar_wait(smem_u32(&mbar[stW]), parW);
            const int nb = r0 + (t + 1) * TILE_P;
            float* ep = sh_ep + ((t + 1) & 1) * (TILE_P * 32);
            const float* rp = raw_p + stW * TILE_P * KK;
            int v = tid;
            int p = v / KK, k = v % KK;
            float e = (nb + p < r1) ? __expf(rp[v]) : 0.0f;
            ep[p * 32 + (k / K_T) * 8 + (k % K_T)] = e;
            dacc0 += e;
            if (tid < TILE_P * KK - NTHREADS) {
                v = tid + NTHREADS;
                p = v / KK; k = v % KK;
                e = (nb + p < r1) ? __expf(rp[v]) : 0.0f;
                ep[p * 32 + (k / K_T) * 8 + (k % K_T)] = e;
                dacc1 += e;
            }
        }

        // ---- FFMA over tile t (4 points per thread) ----
        {
            const float* ep = sh_ep + (t & 1) * (TILE_P * 32);
            const float* rf = raw_f + stC * TILE_P * CC;
#pragma unroll
            for (int p = 0; p < TILE_P / NG; p++) {
                const int pp = g * (TILE_P / NG) + p;
                const ulonglong2* rowf =
                    reinterpret_cast<const ulonglong2*>(&rf[pp * CC + ct * C_T]);
                ulonglong2 fA = rowf[0];
                ulonglong2 fB = rowf[1];
                float4 e03 = *reinterpret_cast<const float4*>(&ep[pp * 32 + kt * 8]);
                float  e4  = ep[pp * 32 + kt * 8 + 4];
                unsigned long long e2[K_T];
                e2[0] = pack2(e03.x, e03.x);
                e2[1] = pack2(e03.y, e03.y);
                e2[2] = pack2(e03.z, e03.z);
                e2[3] = pack2(e03.w, e03.w);
                e2[4] = pack2(e4, e4);
#pragma unroll
                for (int j = 0; j < K_T; j++) {
                    acc[j][0] = fma2(e2[j], fA.x, acc[j][0]);
                    acc[j][1] = fma2(e2[j], fA.y, acc[j][1]);
                    acc[j][2] = fma2(e2[j], fB.x, acc[j][2]);
                    acc[j][3] = fma2(e2[j], fB.y, acc[j][3]);
                }
            }
        }
        __syncthreads();   // tile t raw_f consumed; exp(t+1) visible for next iter

        // issue tile t+NSTAGE into the just-freed stage
        if (tid == 0 && t + NSTAGE < T) {
            int nb = r0 + (t + NSTAGE) * TILE_P;
            int rows = min(TILE_P, N - nb);
            unsigned fb = rows * CC * 4;
            unsigned pb = rows * KK * 4;
            unsigned mb = smem_u32(&mbar[isSt]);
            mbar_expect_tx(mb, fb + pb);
            bulk_g2s(smem_u32(&raw_f[isSt * TILE_P * CC]),
                     feats + (long long)nb * CC, fb, mb);
            bulk_g2s(smem_u32(&raw_p[isSt * TILE_P * KK]),
                     probs + (long long)nb * KK, pb, mb);
        }
        if (++stW == NSTAGE) { stW = 0; parW ^= 1; }
        if (++stC == NSTAGE) stC = 0;
        if (++isSt == NSTAGE) isSt = 0;
    }

    // ---- denom reduction ----
    atomicAdd(&sh_dk[tid % KK], dacc0);
    if (tid < TILE_P * KK - NTHREADS)
        atomicAdd(&sh_dk[(tid + NTHREADS) % KK], dacc1);

    // ---- epilogue: all 8 groups dump to scratch (reuse raw_f), one sync, sum ----
    float* scratch = raw_f;   // NSTAGE*TILE_P*CC = 15360 = NG * KK * CC floats
    {
        const int base = g * (KK * CC) + kt * K_T * CC + ct * C_T;
#pragma unroll
        for (int j = 0; j < K_T; j++) {
            float a0, a1, a2, a3, a4, a5, a6, a7;
            unpack2(acc[j][0], a0, a1);
            unpack2(acc[j][1], a2, a3);
            unpack2(acc[j][2], a4, a5);
            unpack2(acc[j][3], a6, a7);
            *reinterpret_cast<float4*>(&scratch[base + j * CC]) =
                make_float4(a0, a1, a2, a3);
            *reinterpret_cast<float4*>(&scratch[base + j * CC + 4]) =
                make_float4(a4, a5, a6, a7);
        }
    }
    __syncthreads();

    {
        float* outp = g_part + blockIdx.x * (KK * CC);
#pragma unroll
        for (int i = 0; i < (KK * CC) / NTHREADS; i++) {
            int o = tid + i * NTHREADS;
            float sum = 0.0f;
#pragma unroll
            for (int gg = 0; gg < NG; gg++)
                sum += scratch[gg * (KK * CC) + o];
            outp[o] = sum;
        }
    }
    if (tid < KK)
        g_pden[blockIdx.x * KK + tid] = sh_dk[tid];
}

// ---------------------------------------------------------------------------
// reduce v4: one block per (b,k); 8 s-slices x 96 channels; smem combine.
// ---------------------------------------------------------------------------
__global__ void __launch_bounds__(768)
reduce_kernel(float* __restrict__ out) {
    const int bk = blockIdx.x;          // B*KK blocks
    const int b = bk / KK, k = bk % KK;
    const int sg = threadIdx.x / CC;    // 0..7
    const int c  = threadIdx.x % CC;

    __shared__ float red[8][CC];
    __shared__ float den[8];

    float v = 0.0f, d = 0.0f;
    for (int s = sg; s < SPLITS; s += 8) {
        v += g_part[((b * SPLITS + s) * KK + k) * CC + c];
        if (c == 0) d += g_pden[(b * SPLITS + s) * KK + k];
    }
    red[sg][c] = v;
    if (c == 0) den[sg] = d;
    __syncthreads();

    if (threadIdx.x < CC) {
        float vv = 0.0f, dd = 0.0f;
#pragma unroll
        for (int i = 0; i < 8; i++) { vv += red[i][c]; dd += den[i]; }
        out[bk * CC + c] = (dd > 0.0f) ? vv / dd : 0.0f;
    }
}

// ---------------------------------------------------------------------------
extern "C" void kernel_launch(void* const* d_in, const int* in_sizes, int n_in,
                              void* d_out, int out_size) {
    const float* feats = (const float*)d_in[0];   // [N, C]
    const float* probs = (const float*)d_in[1];   // [N, K]
    const int*   bidx  = (const int*)d_in[3];     // [N], sorted
    float* out = (float*)d_out;                   // [B, K, C]

    const int N = in_sizes[3];
    const int B = out_size / (KK * CC);

    cudaFuncSetAttribute(gather_kernel,
                         cudaFuncAttributeMaxDynamicSharedMemorySize, SMEM_BYTES);
    gather_kernel<<<B * SPLITS, NTHREADS, SMEM_BYTES>>>(feats, probs, bidx, N);
    reduce_kernel<<<B * KK, 768>>>(out);
}